// round 15
// baseline (speedup 1.0000x reference)
#include <cuda_runtime.h>
#include <cuda_fp16.h>
#include <cstdint>

// Problem constants (fixed by setup_inputs)
#define TT    2048
#define DD    1024
#define HH    16
#define HDIM  64
#define BB    4
#define NBH   64        // B*H
#define MROWS 8192      // B*T

// ---------------- scratch (no cudaMalloc allowed) ----------------
__device__ uint4 g_aF[(size_t)512 * 64 * 32];      // A fragments [mb][ks][lane]; x-frags for hgemm<0>, ctx-frags for hgemm<1>
__device__ uint4 g_wF[(size_t)4 * 64 * 64 * 32];   // W fragments [z][nb][ks][lane]
__device__ uint4 g_qF[(size_t)NBH * 128 * 4 * 32]; // Q A-fragments [bh][t16][d16][lane]
__device__ __align__(16) __half g_kf[(size_t)NBH * TT * HDIM];   // [bh][t][d]
__device__ __align__(16) __half g_vTf[(size_t)NBH * HDIM * TT];  // [bh][d][t]

// ---------------- PTX helpers ----------------
__device__ __forceinline__ void mma_f16(float* c, const unsigned* a, const unsigned* b) {
    asm volatile(
        "mma.sync.aligned.m16n8k16.row.col.f32.f16.f16.f32 "
        "{%0,%1,%2,%3}, {%4,%5,%6,%7}, {%8,%9}, {%0,%1,%2,%3};\n"
        : "+f"(c[0]), "+f"(c[1]), "+f"(c[2]), "+f"(c[3])
        : "r"(a[0]), "r"(a[1]), "r"(a[2]), "r"(a[3]), "r"(b[0]), "r"(b[1]));
}

__device__ __forceinline__ void ldsm_x4(unsigned* r, unsigned addr) {
    asm volatile("ldmatrix.sync.aligned.m8n8.x4.shared.b16 {%0,%1,%2,%3}, [%4];\n"
                 : "=r"(r[0]), "=r"(r[1]), "=r"(r[2]), "=r"(r[3]) : "r"(addr));
}

__device__ __forceinline__ void cp16(unsigned smem, const void* g) {
    asm volatile("cp.async.ca.shared.global [%0], [%1], 16;\n" :: "r"(smem), "l"(g));
}
#define CP_COMMIT()  asm volatile("cp.async.commit_group;\n" ::: "memory")
#define CP_WAIT_1()  asm volatile("cp.async.wait_group 1;\n" ::: "memory")
#define CP_WAIT_0()  asm volatile("cp.async.wait_group 0;\n" ::: "memory")

__device__ __forceinline__ float ex2(float x) {
    float y; asm("ex2.approx.ftz.f32 %0, %1;\n" : "=f"(y) : "f"(x)); return y;
}

__device__ __forceinline__ unsigned h2ex2(unsigned x) {
    unsigned y; asm("ex2.approx.f16x2 %0, %1;\n" : "=r"(y) : "r"(x)); return y;
}

__device__ __forceinline__ unsigned pack_h2(float a, float b) {
    __half2 h = __floats2half2_rn(a, b);
    return *(unsigned*)&h;
}

#define QSCALE (0.125f * 1.4426950408889634f)   // hd^-0.5 * log2(e)

// ---------------- fragment-builder kernels ----------------
// x [m][k] fp32 -> A fragment blocks g_aF[mb][ks][lane]
__global__ void __launch_bounds__(256) conv_aF(const float* __restrict__ xin) {
    const int m0 = blockIdx.x * 128;
    const int k0 = blockIdx.y * 64;
    __shared__ __align__(16) char csm[4 * 6144];   // 4 k16 slabs, 128 rows x 48B
    const unsigned cb = (unsigned)__cvta_generic_to_shared(csm);
    const int tid = threadIdx.x;

    for (int i = 0; i < 32; i++) {
        int idx = tid + i * 256;              // 128m x 64k
        int m = idx >> 6, k = idx & 63;
        __half h = __float2half_rn(xin[(size_t)(m0 + m) * DD + k0 + k]);
        int slab = k >> 4, klo = k & 15;
        *(__half*)(csm + slab * 6144 + m * 48 + ((klo & 7) << 1) + ((klo >> 3) << 4)) = h;
    }
    __syncthreads();

    const int w = tid >> 5, lane = tid & 31;   // warp w -> m16 block w
#pragma unroll
    for (int s = 0; s < 4; s++) {
        unsigned afr[4];
        unsigned addr = cb + s * 6144 +
            (unsigned)((w * 16 + (lane & 15)) * 48 + ((lane >> 4) << 4));
        ldsm_x4(afr, addr);
        uint4 o4; o4.x = afr[0]; o4.y = afr[1]; o4.z = afr[2]; o4.w = afr[3];
        g_aF[(((size_t)(m0 >> 4) + w) * 64 + (k0 >> 4) + s) * 32 + lane] = o4;
    }
}

// W [k][n] row-major -> B fragment blocks g_wF[z][nb][ks][lane]
__global__ void __launch_bounds__(256) conv_wF(
    const float* __restrict__ Wq, const float* __restrict__ Wk,
    const float* __restrict__ Wv, const float* __restrict__ Wo)
{
    const int z = blockIdx.z;
    const float* W = (z == 0) ? Wq : (z == 1) ? Wk : (z == 2) ? Wv : Wo;
    const int n0 = blockIdx.x * 128;
    const int k0 = blockIdx.y * 64;
    __shared__ __align__(16) char csm[4 * 6144];
    const unsigned cb = (unsigned)__cvta_generic_to_shared(csm);
    const int tid = threadIdx.x;

    for (int i = 0; i < 32; i++) {
        int idx = tid + i * 256;
        int k = idx >> 7, n = idx & 127;
        float w = W[(size_t)(k0 + k) * DD + n0 + n];
        int slab = k >> 4, klo = k & 15;
        *(__half*)(csm + slab * 6144 + n * 48 + ((klo & 7) << 1) + ((klo >> 3) << 4)) =
            __float2half_rn(w);
    }
    __syncthreads();

    const int w = tid >> 5, lane = tid & 31;
#pragma unroll
    for (int s = 0; s < 4; s++) {
        unsigned bfr[4];
        unsigned addr = cb + s * 6144 +
            (unsigned)((w * 16 + ((lane >> 4) << 3) + (lane & 7)) * 48 +
                       (((lane >> 3) & 1) << 4));
        ldsm_x4(bfr, addr);
        uint4 o4; o4.x = bfr[0]; o4.y = bfr[1]; o4.z = bfr[2]; o4.w = bfr[3];
        g_wF[(((size_t)z * 64 + (n0 >> 4) + w) * 64 + (k0 >> 4) + s) * 32 + lane] = o4;
    }
}

// ---------------------------------------------------------------------------
// fp16 tensor-core GEMM, zero shared memory (as R14).
// MODE 0: QKV. z==0 epilogue writes Q ATTN FRAGMENTS (g_qF) directly;
//         z==1 -> g_kf rows; z==2 -> g_vTf transposed rows.
// MODE 1: out projection (fp32 out + bias), A read from g_aF (ctx frags).
// ---------------------------------------------------------------------------
template<int MODE>
__global__ void __launch_bounds__(256, 2) hgemm(
    const float* __restrict__ biasA, const float* __restrict__ biasB,
    const float* __restrict__ biasC, float* __restrict__ outp)
{
    const int z = (MODE == 0) ? blockIdx.z : 3;
    const float* bias = (MODE == 0) ? ((z == 0) ? biasA : (z == 1) ? biasB : biasC)
                                    : biasA;

    const int t = threadIdx.x;
    const int bm = blockIdx.y << 7;
    const int bn = blockIdx.x << 7;
    const int wid = t >> 5, lane = t & 31;
    const int wm = (wid & 1) << 6;
    const int wn = (wid >> 1) << 5;

    float acc[4][4][4];
#pragma unroll
    for (int i = 0; i < 4; i++)
#pragma unroll
        for (int j = 0; j < 4; j++)
#pragma unroll
            for (int r = 0; r < 4; r++) acc[i][j][r] = 0.f;

    const uint4* aP  = g_aF + ((size_t)((bm + wm) >> 4) * 64) * 32 + lane;
    const uint4* b0p = g_wF + (((size_t)z * 64 + (bn >> 4) + (wn >> 4)) * 64) * 32 + lane;
    const uint4* b1p = b0p + 64 * 32;

    const int NIT = DD / 32;
    for (int it = 0; it < NIT; ++it) {
        uint4 a[8];
#pragma unroll
        for (int i = 0; i < 4; i++) {
            a[2 * i]     = aP[(size_t)i * 64 * 32];
            a[2 * i + 1] = aP[(size_t)i * 64 * 32 + 32];
        }
        uint4 b[4];
        b[0] = b0p[0];  b[1] = b1p[0];
        b[2] = b0p[32]; b[3] = b1p[32];

#pragma unroll
        for (int s = 0; s < 2; s++) {
            unsigned bfr[8];
            *(uint4*)(bfr)     = b[s * 2];
            *(uint4*)(bfr + 4) = b[s * 2 + 1];
#pragma unroll
            for (int i = 0; i < 4; i++) {
                const unsigned* afr = (const unsigned*)&a[2 * i + s];
#pragma unroll
                for (int j = 0; j < 4; j++)
                    mma_f16(acc[i][j], afr, bfr + 2 * j);
            }
        }
        aP  += 2 * 32;
        b0p += 2 * 32;
        b1p += 2 * 32;
    }

    const int gg = lane >> 2, tg = lane & 3;

    if (MODE == 0 && z == 0) {
        // Q: write attn-ready A fragments (C-layout == A-fragment identity)
#pragma unroll
        for (int i = 0; i < 4; i++) {
            const int rowb = bm + wm + 16 * i;       // m16 block base
            const int t16  = (rowb & 2047) >> 4;
            const int b0_  = rowb >> 11;
#pragma unroll
            for (int cp = 0; cp < 2; cp++) {
                const int j0 = 2 * cp, j1 = j0 + 1;
                const int col0 = bn + wn + 8 * j0 + 2 * tg;
                const int col1 = col0 + 8;
                float a00 = (acc[i][j0][0] + bias[col0])     * QSCALE;
                float a01 = (acc[i][j0][1] + bias[col0 + 1]) * QSCALE;
                float a10 = (acc[i][j0][2] + bias[col0])     * QSCALE;
                float a11 = (acc[i][j0][3] + bias[col0 + 1]) * QSCALE;
                float c00 = (acc[i][j1][0] + bias[col1])     * QSCALE;
                float c01 = (acc[i][j1][1] + bias[col1 + 1]) * QSCALE;
                float c10 = (acc[i][j1][2] + bias[col1])     * QSCALE;
                float c11 = (acc[i][j1][3] + bias[col1 + 1]) * QSCALE;
                const int head  = col0 >> 6;
                const int chunk = (col0 & 63) >> 4;
                const int bh_   = b0_ * 16 + head;
                uint4 o4;
                o4.x = pack_h2(a00, a01);   // (r, klow)
                o4.y = pack_h2(a10, a11);   // (r+8, klow)
                o4.z = pack_h2(c00, c01);   // (r, k+8)
                o4.w = pack_h2(c10, c11);   // (r+8, k+8)
                g_qF[(((size_t)bh_ * 128 + t16) * 4 + chunk) * 32 + lane] = o4;
            }
        }
        return;
    }

#pragma unroll
    for (int i = 0; i < 4; i++) {
#pragma unroll
        for (int j = 0; j < 4; j++) {
            const int row = bm + wm + 16 * i + gg;
            const int col = bn + wn + 8 * j + 2 * tg;
            float v00 = acc[i][j][0] + bias[col];
            float v01 = acc[i][j][1] + bias[col + 1];
            float v10 = acc[i][j][2] + bias[col];
            float v11 = acc[i][j][3] + bias[col + 1];
            if (MODE == 0) {
                const int head = col >> 6, d = col & 63;
                const int b0_ = row >> 11, t0_ = row & 2047;
                const int t1_ = (row + 8) & 2047;
                const int bh_ = b0_ * 16 + head;
                if (z == 2) {
                    size_t r0 = ((size_t)bh_ * 64 + d) * 2048;
                    size_t r1 = ((size_t)bh_ * 64 + d + 1) * 2048;
                    g_vTf[r0 + t0_] = __float2half_rn(v00);
                    g_vTf[r1 + t0_] = __float2half_rn(v01);
                    g_vTf[r0 + t1_] = __float2half_rn(v10);
                    g_vTf[r1 + t1_] = __float2half_rn(v11);
                } else {   // z == 1 : K rows
                    size_t o0 = ((size_t)bh_ * 2048 + t0_) * 64 + d;
                    size_t o1 = ((size_t)bh_ * 2048 + t1_) * 64 + d;
                    *(unsigned*)(g_kf + o0) = pack_h2(v00, v01);
                    *(unsigned*)(g_kf + o1) = pack_h2(v10, v11);
                }
            } else {
                outp[(size_t)row * DD + col]           = v00;
                outp[(size_t)row * DD + col + 1]       = v01;
                outp[(size_t)(row + 8) * DD + col]     = v10;
                outp[(size_t)(row + 8) * DD + col + 1] = v11;
            }
        }
    }
}

// ---------------------------------------------------------------------------
// fp16 tensor-core BD3LM attention, m32 warps. Block = (bh, 128-row q-tile),
// 128 threads / 4 warps, warp w = q rows [32w, 32w+32). K tiles [kv][64] and
// V^T tiles [d][kv] in smem (3-buffer cp.async); Q via prebuilt fragments
// (LDG); epilogue writes hgemm A-fragments (g_aF) directly.
// Unified mask: cmp((coff+c)>>2, r>>2), coff in {0,64}.
// ---------------------------------------------------------------------------
#define AT_PITCH  144
#define AT_ARR    (64 * AT_PITCH)     // 9216
#define AT_BUF    (2 * AT_ARR)        // 18432 (K, V)
#define AT_SMEM   (3 * AT_BUF)        // 55296

__global__ void __launch_bounds__(128, 2) attn_mma()
{
    extern __shared__ __align__(16) char dsm[];
    const unsigned sb = (unsigned)__cvta_generic_to_shared(dsm);

    const int bi = blockIdx.x;                 // 0..15, heavy-first
    const int u   = 7 - (bi >> 1);
    const int rgn = bi & 1;                    // 0 = xt, 1 = x0
    const int bh  = blockIdx.y;
    const int qbase = (rgn ? 1024 : 0) + 128 * u;   // bh-local t of q row 0
    const int ntiles = rgn ? (2 * u + 2) : (2 * u + 4);

    const int tid = threadIdx.x;
    const int lane = tid & 31, warp = tid >> 5;
    const int g = lane >> 2, tq = lane & 3;

    // ---- Q fragments via LDG (prebuilt by hgemm<0> z==0) ----
    unsigned qf[2][4][4];
#pragma unroll
    for (int i = 0; i < 2; i++) {
        const size_t t16 = (size_t)bh * 128 + ((qbase + 32 * warp + 16 * i) >> 4);
#pragma unroll
        for (int c = 0; c < 4; c++) {
            uint4 v = g_qF[(t16 * 4 + c) * 32 + lane];
            qf[i][c][0] = v.x; qf[i][c][1] = v.y; qf[i][c][2] = v.z; qf[i][c][3] = v.w;
        }
    }

    float o[2][8][4];
#pragma unroll
    for (int i = 0; i < 2; i++)
#pragma unroll
        for (int j = 0; j < 8; j++)
#pragma unroll
            for (int k = 0; k < 4; k++) o[i][j][k] = 0.f;
    float osum[2][4] = {{0.f, 0.f, 0.f, 0.f}, {0.f, 0.f, 0.f, 0.f}};
    float m[2][2] = {{-1e30f, -1e30f}, {-1e30f, -1e30f}};

    // tile -> (kv start s, mode, coff). mode: 0 full, 1 LE, 2 LT, 3 EQ
    auto tile_of = [&](int it, int& s, int& mode, int& coff) {
        if (it < 2 * u)        { s = 1024 + 64 * it; mode = 0; coff = 0; }
        else if (rgn)          { s = 1024 + 64 * it; mode = 1; coff = 64 * (it - 2 * u); }
        else if (it < 2 * u + 2){ s = 1024 + 64 * it; mode = 2; coff = 64 * (it - 2 * u); }
        else                   { s = 128 * u + 64 * (it - 2 * u - 2); mode = 3;
                                 coff = 64 * (it - 2 * u - 2); }
    };

    auto prefetch = [&](int s, int buf) {
        unsigned dstb = sb + buf * AT_BUF;
#pragma unroll
        for (int i = 0; i < 8; i++) {
            int idx = tid + (i << 7);
            int arr = idx >> 9, rem = idx & 511;
            int r = rem >> 3, c = rem & 7;
            const __half* src = (arr == 0)
                ? g_kf  + ((size_t)bh * 2048 + s + r) * 64 + c * 8
                : g_vTf + ((size_t)bh * 64 + r) * 2048 + s + c * 8;
            cp16(dstb + arr * AT_ARR + r * AT_PITCH + c * 16, src);
        }
    };

    {
        int s0, md, co;
        tile_of(0, s0, md, co); prefetch(s0, 0); CP_COMMIT();
        tile_of(1, s0, md, co); prefetch(s0, 1); CP_COMMIT();
    }

    const unsigned b_off = (unsigned)((((lane >> 4) << 3) + (lane & 7)) * AT_PITCH +
                                      (((lane >> 3) & 1) << 4));
    const unsigned onesb[2] = {0x3C003C00u, 0x3C003C00u};

    for (int it = 0; it < ntiles; ++it) {
        int s_, mode, coff; tile_of(it, s_, mode, coff);
        if (it < ntiles - 1) { CP_WAIT_1(); } else { CP_WAIT_0(); }
        __syncthreads();

        const unsigned base = sb + (it % 3) * AT_BUF;

        // ---- S = Q K^T (both m16 blocks share each kb) ----
        float sc[2][8][4];
#pragma unroll
        for (int i = 0; i < 2; i++)
#pragma unroll
            for (int j = 0; j < 8; j++)
#pragma unroll
                for (int k = 0; k < 4; k++) sc[i][j][k] = 0.f;

#pragma unroll
        for (int c = 0; c < 4; c++) {
#pragma unroll
            for (int p = 0; p < 4; p++) {
                unsigned kb[4];
                ldsm_x4(kb, base + (p << 4) * AT_PITCH + b_off + c * 32);
#pragma unroll
                for (int i = 0; i < 2; i++) {
                    mma_f16(sc[i][2 * p],     qf[i][c], kb);
                    mma_f16(sc[i][2 * p + 1], qf[i][c], kb + 2);
                }
            }
        }

        // ---- mask ----
        if (mode) {
#pragma unroll
            for (int i = 0; i < 2; i++)
#pragma unroll
                for (int j = 0; j < 8; j++)
#pragma unroll
                    for (int k = 0; k < 4; k++) {
                        int r = 32 * warp + 16 * i + g + ((k >> 1) << 3);
                        int c = coff + (j << 3) + (tq << 1) + (k & 1);
                        int rb = r >> 2, cb = c >> 2;
                        bool ok = (mode == 1) ? (cb <= rb) :
                                  (mode == 2) ? (cb <  rb) : (cb == rb);
                        if (!ok) sc[i][j][k] = -1e30f;
                    }
        }

        // ---- online softmax per m16 block ----
        unsigned ph[2][8], pl[2][8];
#pragma unroll
        for (int i = 0; i < 2; i++) {
            float t0 = -1e30f, t1 = -1e30f;
#pragma unroll
            for (int j = 0; j < 8; j++) {
                t0 = fmaxf(t0, fmaxf(sc[i][j][0], sc[i][j][1]));
                t1 = fmaxf(t1, fmaxf(sc[i][j][2], sc[i][j][3]));
            }
            t0 = fmaxf(t0, __shfl_xor_sync(0xffffffffu, t0, 1));
            t0 = fmaxf(t0, __shfl_xor_sync(0xffffffffu, t0, 2));
            t1 = fmaxf(t1, __shfl_xor_sync(0xffffffffu, t1, 1));
            t1 = fmaxf(t1, __shfl_xor_sync(0xffffffffu, t1, 2));
            const float mn0 = fmaxf(m[i][0], t0), mn1 = fmaxf(m[i][1], t1);
            const float r0 = ex2(m[i][0] - mn0), r1 = ex2(m[i][1] - mn1);
            m[i][0] = mn0; m[i][1] = mn1;
#pragma unroll
            for (int j = 0; j < 8; j++) {
                ph[i][j] = h2ex2(pack_h2(sc[i][j][0] - mn0, sc[i][j][1] - mn0));
                pl[i][j] = h2ex2(pack_h2(sc[i][j][2] - mn1, sc[i][j][3] - mn1));
            }
#pragma unroll
            for (int j = 0; j < 8; j++) {
                o[i][j][0] *= r0; o[i][j][1] *= r0;
                o[i][j][2] *= r1; o[i][j][3] *= r1;
            }
            osum[i][0] *= r0; osum[i][1] *= r0;
            osum[i][2] *= r1; osum[i][3] *= r1;
        }

        // ---- O += P V ; osum += P @ ones ----
#pragma unroll
        for (int c = 0; c < 4; c++) {
            unsigned pf0[4], pf1[4];
            pf0[0] = ph[0][2 * c];     pf0[1] = pl[0][2 * c];
            pf0[2] = ph[0][2 * c + 1]; pf0[3] = pl[0][2 * c + 1];
            pf1[0] = ph[1][2 * c];     pf1[1] = pl[1][2 * c];
            pf1[2] = ph[1][2 * c + 1]; pf1[3] = pl[1][2 * c + 1];
            mma_f16(osum[0], pf0, onesb);
            mma_f16(osum[1], pf1, onesb);
#pragma unroll
            for (int p = 0; p < 4; p++) {
                unsigned vb[4];
                ldsm_x4(vb, base + AT_ARR + (p << 4) * AT_PITCH + b_off + c * 32);
                mma_f16(o[0][2 * p],     pf0, vb);
                mma_f16(o[0][2 * p + 1], pf0, vb + 2);
                mma_f16(o[1][2 * p],     pf1, vb);
                mma_f16(o[1][2 * p + 1], pf1, vb + 2);
            }
        }

        if (it + 2 < ntiles) {
            int sn, mn, cn; tile_of(it + 2, sn, mn, cn);
            prefetch(sn, (it + 2) % 3);
            CP_COMMIT();
        }
    }

    // ---- epilogue: normalize, write hgemm<1> A-fragments directly ----
    const int b_ = bh >> 4, h_ = bh & 15;
#pragma unroll
    for (int i = 0; i < 2; i++) {
        const float inv0 = 1.f / osum[i][0], inv1 = 1.f / osum[i][2];
        const size_t mb = ((size_t)b_ * 2048 + qbase + 32 * warp + 16 * i) >> 4;
#pragma unroll
        for (int c = 0; c < 4; c++) {
            uint4 w4;
            w4.x = pack_h2(o[i][2 * c][0] * inv0,     o[i][2 * c][1] * inv0);
            w4.y = pack_h2(o[i][2 * c][2] * inv1,     o[i][2 * c][3] * inv1);
            w4.z = pack_h2(o[i][2 * c + 1][0] * inv0, o[i][2 * c + 1][1] * inv0);
            w4.w = pack_h2(o[i][2 * c + 1][2] * inv1, o[i][2 * c + 1][3] * inv1);
            g_aF[(mb * 64 + (h_ * 4 + c)) * 32 + lane] = w4;
        }
    }
}

// ---------------------------------------------------------------------------

extern "C" void kernel_launch(void* const* d_in, const int* in_sizes, int n_in,
                              void* d_out, int out_size)
{
    const float* x  = (const float*)d_in[0];
    const float* Wq = (const float*)d_in[1];
    const float* bq = (const float*)d_in[2];
    const float* Wk = (const float*)d_in[3];
    const float* bk = (const float*)d_in[4];
    const float* Wv = (const float*)d_in[5];
    const float* bv = (const float*)d_in[6];
    const float* Wo = (const float*)d_in[7];
    const float* bo = (const float*)d_in[8];

    cudaFuncSetAttribute(attn_mma, cudaFuncAttributeMaxDynamicSharedMemorySize, AT_SMEM);

    conv_aF<<<dim3(64, 16), 256>>>(x);                 // x -> A fragments
    conv_wF<<<dim3(8, 16, 4), 256>>>(Wq, Wk, Wv, Wo);

    hgemm<0><<<dim3(8, 64, 3), 256>>>(bq, bk, bv, nullptr);

    attn_mma<<<dim3(16, 64), 128, AT_SMEM>>>();        // overwrites g_aF with ctx frags

    hgemm<1><<<dim3(8, 64), 256>>>(bo, nullptr, nullptr, (float*)d_out);
}

// round 16
// speedup vs baseline: 1.0647x; 1.0647x over previous
#include <cuda_runtime.h>
#include <cuda_fp16.h>
#include <cstdint>

// Problem constants (fixed by setup_inputs)
#define TT    2048
#define DD    1024
#define HH    16
#define HDIM  64
#define BB    4
#define NBH   64        // B*H
#define MROWS 8192      // B*T

// ---------------- scratch (no cudaMalloc allowed) ----------------
__device__ uint4 g_aF[(size_t)512 * 64 * 32];      // A fragments [mb][ks][lane]; x-frags for hgemm<0>, ctx-frags for hgemm<1>
__device__ uint4 g_wF[(size_t)4 * 64 * 64 * 32];   // W fragments [z][nb][ks][lane]
__device__ uint4 g_qF[(size_t)NBH * 128 * 4 * 32]; // Q A-fragments [bh][t16][d16][lane]
__device__ __align__(16) __half g_kf[(size_t)NBH * TT * HDIM];   // [bh][t][d]
__device__ __align__(16) __half g_vTf[(size_t)NBH * HDIM * TT];  // [bh][d][t]

// ---------------- PTX helpers ----------------
__device__ __forceinline__ void mma_f16(float* c, const unsigned* a, const unsigned* b) {
    asm volatile(
        "mma.sync.aligned.m16n8k16.row.col.f32.f16.f16.f32 "
        "{%0,%1,%2,%3}, {%4,%5,%6,%7}, {%8,%9}, {%0,%1,%2,%3};\n"
        : "+f"(c[0]), "+f"(c[1]), "+f"(c[2]), "+f"(c[3])
        : "r"(a[0]), "r"(a[1]), "r"(a[2]), "r"(a[3]), "r"(b[0]), "r"(b[1]));
}

__device__ __forceinline__ void ldsm_x4(unsigned* r, unsigned addr) {
    asm volatile("ldmatrix.sync.aligned.m8n8.x4.shared.b16 {%0,%1,%2,%3}, [%4];\n"
                 : "=r"(r[0]), "=r"(r[1]), "=r"(r[2]), "=r"(r[3]) : "r"(addr));
}

__device__ __forceinline__ void cp16(unsigned smem, const void* g) {
    asm volatile("cp.async.ca.shared.global [%0], [%1], 16;\n" :: "r"(smem), "l"(g));
}
#define CP_COMMIT()  asm volatile("cp.async.commit_group;\n" ::: "memory")
#define CP_WAIT_1()  asm volatile("cp.async.wait_group 1;\n" ::: "memory")
#define CP_WAIT_0()  asm volatile("cp.async.wait_group 0;\n" ::: "memory")

__device__ __forceinline__ float ex2(float x) {
    float y; asm("ex2.approx.ftz.f32 %0, %1;\n" : "=f"(y) : "f"(x)); return y;
}

__device__ __forceinline__ unsigned h2ex2(unsigned x) {
    unsigned y; asm("ex2.approx.f16x2 %0, %1;\n" : "=r"(y) : "r"(x)); return y;
}

__device__ __forceinline__ unsigned pack_h2(float a, float b) {
    __half2 h = __floats2half2_rn(a, b);
    return *(unsigned*)&h;
}

#define QSCALE (0.125f * 1.4426950408889634f)   // hd^-0.5 * log2(e)

// ---------------- fragment-builder kernels ----------------
// x [m][k] fp32 -> A fragment blocks g_aF[mb][ks][lane]
__global__ void __launch_bounds__(256) conv_aF(const float* __restrict__ xin) {
    const int m0 = blockIdx.x * 128;
    const int k0 = blockIdx.y * 64;
    __shared__ __align__(16) char csm[4 * 6144];   // 4 k16 slabs, 128 rows x 48B
    const unsigned cb = (unsigned)__cvta_generic_to_shared(csm);
    const int tid = threadIdx.x;

    for (int i = 0; i < 32; i++) {
        int idx = tid + i * 256;              // 128m x 64k
        int m = idx >> 6, k = idx & 63;
        __half h = __float2half_rn(xin[(size_t)(m0 + m) * DD + k0 + k]);
        int slab = k >> 4, klo = k & 15;
        *(__half*)(csm + slab * 6144 + m * 48 + ((klo & 7) << 1) + ((klo >> 3) << 4)) = h;
    }
    __syncthreads();

    const int w = tid >> 5, lane = tid & 31;   // warp w -> m16 block w
#pragma unroll
    for (int s = 0; s < 4; s++) {
        unsigned afr[4];
        unsigned addr = cb + s * 6144 +
            (unsigned)((w * 16 + (lane & 15)) * 48 + ((lane >> 4) << 4));
        ldsm_x4(afr, addr);
        uint4 o4; o4.x = afr[0]; o4.y = afr[1]; o4.z = afr[2]; o4.w = afr[3];
        g_aF[(((size_t)(m0 >> 4) + w) * 64 + (k0 >> 4) + s) * 32 + lane] = o4;
    }
}

// W [k][n] row-major -> B fragment blocks g_wF[z][nb][ks][lane]
__global__ void __launch_bounds__(256) conv_wF(
    const float* __restrict__ Wq, const float* __restrict__ Wk,
    const float* __restrict__ Wv, const float* __restrict__ Wo)
{
    const int z = blockIdx.z;
    const float* W = (z == 0) ? Wq : (z == 1) ? Wk : (z == 2) ? Wv : Wo;
    const int n0 = blockIdx.x * 128;
    const int k0 = blockIdx.y * 64;
    __shared__ __align__(16) char csm[4 * 6144];
    const unsigned cb = (unsigned)__cvta_generic_to_shared(csm);
    const int tid = threadIdx.x;

    for (int i = 0; i < 32; i++) {
        int idx = tid + i * 256;
        int k = idx >> 7, n = idx & 127;
        float w = W[(size_t)(k0 + k) * DD + n0 + n];
        int slab = k >> 4, klo = k & 15;
        *(__half*)(csm + slab * 6144 + n * 48 + ((klo & 7) << 1) + ((klo >> 3) << 4)) =
            __float2half_rn(w);
    }
    __syncthreads();

    const int w = tid >> 5, lane = tid & 31;
#pragma unroll
    for (int s = 0; s < 4; s++) {
        unsigned bfr[4];
        unsigned addr = cb + s * 6144 +
            (unsigned)((w * 16 + ((lane >> 4) << 3) + (lane & 7)) * 48 +
                       (((lane >> 3) & 1) << 4));
        ldsm_x4(bfr, addr);
        uint4 o4; o4.x = bfr[0]; o4.y = bfr[1]; o4.z = bfr[2]; o4.w = bfr[3];
        g_wF[(((size_t)z * 64 + (n0 >> 4) + w) * 64 + (k0 >> 4) + s) * 32 + lane] = o4;
    }
}

// ---------------------------------------------------------------------------
// fp16 tensor-core GEMM, zero shared memory (as R14).
// MODE 0: QKV. z==0 epilogue writes Q ATTN FRAGMENTS (g_qF) directly;
//         z==1 -> g_kf rows; z==2 -> g_vTf transposed rows.
// MODE 1: out projection (fp32 out + bias), A read from g_aF (ctx frags).
// ---------------------------------------------------------------------------
template<int MODE>
__global__ void __launch_bounds__(256, 2) hgemm(
    const float* __restrict__ biasA, const float* __restrict__ biasB,
    const float* __restrict__ biasC, float* __restrict__ outp)
{
    const int z = (MODE == 0) ? blockIdx.z : 3;
    const float* bias = (MODE == 0) ? ((z == 0) ? biasA : (z == 1) ? biasB : biasC)
                                    : biasA;

    const int t = threadIdx.x;
    const int bm = blockIdx.y << 7;
    const int bn = blockIdx.x << 7;
    const int wid = t >> 5, lane = t & 31;
    const int wm = (wid & 1) << 6;
    const int wn = (wid >> 1) << 5;

    float acc[4][4][4];
#pragma unroll
    for (int i = 0; i < 4; i++)
#pragma unroll
        for (int j = 0; j < 4; j++)
#pragma unroll
            for (int r = 0; r < 4; r++) acc[i][j][r] = 0.f;

    const uint4* aP  = g_aF + ((size_t)((bm + wm) >> 4) * 64) * 32 + lane;
    const uint4* b0p = g_wF + (((size_t)z * 64 + (bn >> 4) + (wn >> 4)) * 64) * 32 + lane;
    const uint4* b1p = b0p + 64 * 32;

    const int NIT = DD / 32;
    for (int it = 0; it < NIT; ++it) {
        uint4 a[8];
#pragma unroll
        for (int i = 0; i < 4; i++) {
            a[2 * i]     = aP[(size_t)i * 64 * 32];
            a[2 * i + 1] = aP[(size_t)i * 64 * 32 + 32];
        }
        uint4 b[4];
        b[0] = b0p[0];  b[1] = b1p[0];
        b[2] = b0p[32]; b[3] = b1p[32];

#pragma unroll
        for (int s = 0; s < 2; s++) {
            unsigned bfr[8];
            *(uint4*)(bfr)     = b[s * 2];
            *(uint4*)(bfr + 4) = b[s * 2 + 1];
#pragma unroll
            for (int i = 0; i < 4; i++) {
                const unsigned* afr = (const unsigned*)&a[2 * i + s];
#pragma unroll
                for (int j = 0; j < 4; j++)
                    mma_f16(acc[i][j], afr, bfr + 2 * j);
            }
        }
        aP  += 2 * 32;
        b0p += 2 * 32;
        b1p += 2 * 32;
    }

    const int gg = lane >> 2, tg = lane & 3;

    if (MODE == 0 && z == 0) {
        // Q: write attn-ready A fragments (C-layout == A-fragment identity)
#pragma unroll
        for (int i = 0; i < 4; i++) {
            const int rowb = bm + wm + 16 * i;       // m16 block base
            const int t16  = (rowb & 2047) >> 4;
            const int b0_  = rowb >> 11;
#pragma unroll
            for (int cp = 0; cp < 2; cp++) {
                const int j0 = 2 * cp, j1 = j0 + 1;
                const int col0 = bn + wn + 8 * j0 + 2 * tg;
                const int col1 = col0 + 8;
                float a00 = (acc[i][j0][0] + bias[col0])     * QSCALE;
                float a01 = (acc[i][j0][1] + bias[col0 + 1]) * QSCALE;
                float a10 = (acc[i][j0][2] + bias[col0])     * QSCALE;
                float a11 = (acc[i][j0][3] + bias[col0 + 1]) * QSCALE;
                float c00 = (acc[i][j1][0] + bias[col1])     * QSCALE;
                float c01 = (acc[i][j1][1] + bias[col1 + 1]) * QSCALE;
                float c10 = (acc[i][j1][2] + bias[col1])     * QSCALE;
                float c11 = (acc[i][j1][3] + bias[col1 + 1]) * QSCALE;
                const int head  = col0 >> 6;
                const int chunk = (col0 & 63) >> 4;
                const int bh_   = b0_ * 16 + head;
                uint4 o4;
                o4.x = pack_h2(a00, a01);   // (r, klow)
                o4.y = pack_h2(a10, a11);   // (r+8, klow)
                o4.z = pack_h2(c00, c01);   // (r, k+8)
                o4.w = pack_h2(c10, c11);   // (r+8, k+8)
                g_qF[(((size_t)bh_ * 128 + t16) * 4 + chunk) * 32 + lane] = o4;
            }
        }
        return;
    }

#pragma unroll
    for (int i = 0; i < 4; i++) {
#pragma unroll
        for (int j = 0; j < 4; j++) {
            const int row = bm + wm + 16 * i + gg;
            const int col = bn + wn + 8 * j + 2 * tg;
            float v00 = acc[i][j][0] + bias[col];
            float v01 = acc[i][j][1] + bias[col + 1];
            float v10 = acc[i][j][2] + bias[col];
            float v11 = acc[i][j][3] + bias[col + 1];
            if (MODE == 0) {
                const int head = col >> 6, d = col & 63;
                const int b0_ = row >> 11, t0_ = row & 2047;
                const int t1_ = (row + 8) & 2047;
                const int bh_ = b0_ * 16 + head;
                if (z == 2) {
                    size_t r0 = ((size_t)bh_ * 64 + d) * 2048;
                    size_t r1 = ((size_t)bh_ * 64 + d + 1) * 2048;
                    g_vTf[r0 + t0_] = __float2half_rn(v00);
                    g_vTf[r1 + t0_] = __float2half_rn(v01);
                    g_vTf[r0 + t1_] = __float2half_rn(v10);
                    g_vTf[r1 + t1_] = __float2half_rn(v11);
                } else {   // z == 1 : K rows
                    size_t o0 = ((size_t)bh_ * 2048 + t0_) * 64 + d;
                    size_t o1 = ((size_t)bh_ * 2048 + t1_) * 64 + d;
                    *(unsigned*)(g_kf + o0) = pack_h2(v00, v01);
                    *(unsigned*)(g_kf + o1) = pack_h2(v10, v11);
                }
            } else {
                outp[(size_t)row * DD + col]           = v00;
                outp[(size_t)row * DD + col + 1]       = v01;
                outp[(size_t)(row + 8) * DD + col]     = v10;
                outp[(size_t)(row + 8) * DD + col + 1] = v11;
            }
        }
    }
}

// ---------------------------------------------------------------------------
// fp16 tensor-core BD3LM attention — R14 m16-warp structure (proven 79.4us)
// + fusion interfaces: Q from g_qF fragments (LDG, no staging/barriers),
// epilogue writes hgemm<1> A-fragments directly into g_aF.
// Block = (bh, 64-row q-tile), 128 threads / 4 warps (warp = m16).
// K tiles [kv][64], V^T tiles [d][kv], 144B pitch; 3 KV buffers, one
// barrier per tile; softmax via fp16x2 exp + ones-column mma for l.
// ---------------------------------------------------------------------------
#define AT_PITCH  144
#define AT_ARR    (64 * AT_PITCH)     // 9216
#define AT_BUF    (2 * AT_ARR)        // 18432 (K, V)
#define AT_SMEM   (3 * AT_BUF)        // 55296

__global__ void __launch_bounds__(128, 4) attn_mma()
{
    extern __shared__ __align__(16) char dsm[];
    const unsigned sb = (unsigned)__cvta_generic_to_shared(dsm);

    const int bi = blockIdx.x;
    // heavy-first ordering: xt qt has qt+2 tiles, x0 qt has qt-15
    const int qt = (bi & 1) ? (31 - (bi >> 1)) : (15 - (bi >> 1));
    const int bh = blockIdx.y;
    const int qt0 = qt << 6;
    const int tid = threadIdx.x;
    const int lane = tid & 31, warp = tid >> 5;
    const int wm = warp << 4;
    const int g = lane >> 2, tq = lane & 3;

    // ---- Q fragments via LDG (prebuilt by hgemm<0> z==0) ----
    unsigned qf[4][4];
    {
        const size_t t16 = (size_t)bh * 128 + ((qt0 + wm) >> 4);
#pragma unroll
        for (int c = 0; c < 4; c++) {
            uint4 v = g_qF[(t16 * 4 + c) * 32 + lane];
            qf[c][0] = v.x; qf[c][1] = v.y; qf[c][2] = v.z; qf[c][3] = v.w;
        }
    }

    float o[8][4];
#pragma unroll
    for (int j = 0; j < 8; j++)
#pragma unroll
        for (int k = 0; k < 4; k++) o[j][k] = 0.f;
    float osum[4] = {0.f, 0.f, 0.f, 0.f};   // all-ones column: becomes l
    float m0 = -1e30f, m1 = -1e30f;

    const bool is_x0 = (qt >= 16);
    const int nfull  = is_x0 ? (qt - 16) : qt;
    const int ntiles = nfull + (is_x0 ? 1 : 2);

    auto tile_of = [&](int it, int& s, int& mode) {
        if (it < nfull)        { s = 1024 + (it << 6); mode = 0; }
        else if (is_x0)        { s = qt0;              mode = 1; }
        else if (it == nfull)  { s = 1024 + qt0;       mode = 2; }
        else                   { s = qt0;              mode = 3; }
    };

    auto prefetch = [&](int s, int buf) {
        unsigned dstb = sb + buf * AT_BUF;
#pragma unroll
        for (int i = 0; i < 8; i++) {
            int idx = tid + (i << 7);
            int arr = idx >> 9, rem = idx & 511;
            int r = rem >> 3, c = rem & 7;
            const __half* src = (arr == 0)
                ? g_kf  + ((size_t)bh * 2048 + s + r) * 64 + c * 8
                : g_vTf + ((size_t)bh * 64 + r) * 2048 + s + c * 8;
            cp16(dstb + arr * AT_ARR + r * AT_PITCH + c * 16, src);
        }
    };

    {
        int s0, md; tile_of(0, s0, md);
        prefetch(s0, 0);
        CP_COMMIT();
        if (ntiles > 1) { int s1; tile_of(1, s1, md); prefetch(s1, 1); }
        CP_COMMIT();    // commit even if empty: keeps group counting uniform
    }

    const unsigned b_off = (unsigned)((((lane >> 4) << 3) + (lane & 7)) * AT_PITCH +
                                      (((lane >> 3) & 1) << 4));
    const unsigned onesb[2] = {0x3C003C00u, 0x3C003C00u};   // fp16 1.0 x4

    for (int it = 0; it < ntiles; ++it) {
        int s_, mode; tile_of(it, s_, mode);
        if (it < ntiles - 1) { CP_WAIT_1(); } else { CP_WAIT_0(); }
        __syncthreads();   // tile 'it' ready; all warps done reading it-1

        const unsigned base = sb + (it % 3) * AT_BUF;

        // ---- S = Q K^T ----
        float sc[8][4];
#pragma unroll
        for (int j = 0; j < 8; j++)
#pragma unroll
            for (int k = 0; k < 4; k++) sc[j][k] = 0.f;

#pragma unroll
        for (int c = 0; c < 4; c++) {
#pragma unroll
            for (int p = 0; p < 4; p++) {
                unsigned kb[4];
                ldsm_x4(kb, base + (p << 4) * AT_PITCH + b_off + c * 32);
                mma_f16(sc[2 * p],     qf[c], kb);
                mma_f16(sc[2 * p + 1], qf[c], kb + 2);
            }
        }

        // ---- mask (boundary tiles only): block index = idx>>2 ----
        if (mode) {
#pragma unroll
            for (int j = 0; j < 8; j++)
#pragma unroll
                for (int k = 0; k < 4; k++) {
                    int r = wm + g + ((k >> 1) << 3);
                    int c = (j << 3) + (tq << 1) + (k & 1);
                    int r2 = r >> 2, c2 = c >> 2;
                    bool ok = (mode == 1) ? (c2 <= r2) :
                              (mode == 2) ? (c2 <  r2) : (c2 == r2);
                    if (!ok) sc[j][k] = -1e30f;
                }
        }

        // ---- online softmax: max (fp32) then fp16x2 exp -> P fragments ----
        float t0 = -1e30f, t1 = -1e30f;
#pragma unroll
        for (int j = 0; j < 8; j++) {
            t0 = fmaxf(t0, fmaxf(sc[j][0], sc[j][1]));
            t1 = fmaxf(t1, fmaxf(sc[j][2], sc[j][3]));
        }
        t0 = fmaxf(t0, __shfl_xor_sync(0xffffffffu, t0, 1));
        t0 = fmaxf(t0, __shfl_xor_sync(0xffffffffu, t0, 2));
        t1 = fmaxf(t1, __shfl_xor_sync(0xffffffffu, t1, 1));
        t1 = fmaxf(t1, __shfl_xor_sync(0xffffffffu, t1, 2));
        const float mn0 = fmaxf(m0, t0), mn1 = fmaxf(m1, t1);
        const float r0 = ex2(m0 - mn0), r1 = ex2(m1 - mn1);
        m0 = mn0; m1 = mn1;

        unsigned ph[8], pl[8];   // P fp16x2: rows g / g+8
#pragma unroll
        for (int j = 0; j < 8; j++) {
            ph[j] = h2ex2(pack_h2(sc[j][0] - mn0, sc[j][1] - mn0));
            pl[j] = h2ex2(pack_h2(sc[j][2] - mn1, sc[j][3] - mn1));
        }

        // rescale accumulators (osum follows the same recurrence -> final l)
#pragma unroll
        for (int j = 0; j < 8; j++) {
            o[j][0] *= r0; o[j][1] *= r0;
            o[j][2] *= r1; o[j][3] *= r1;
        }
        osum[0] *= r0; osum[1] *= r0;
        osum[2] *= r1; osum[3] *= r1;

        // ---- O += P V ; osum += P @ ones ----
#pragma unroll
        for (int c = 0; c < 4; c++) {
            unsigned pf[4];
            pf[0] = ph[2 * c];     pf[1] = pl[2 * c];
            pf[2] = ph[2 * c + 1]; pf[3] = pl[2 * c + 1];
            mma_f16(osum, pf, onesb);
#pragma unroll
            for (int p = 0; p < 4; p++) {
                unsigned vb[4];
                ldsm_x4(vb, base + AT_ARR + (p << 4) * AT_PITCH + b_off + c * 32);
                mma_f16(o[2 * p],     pf, vb);
                mma_f16(o[2 * p + 1], pf, vb + 2);
            }
        }

        if (it + 2 < ntiles) {   // refill buffer consumed at it-1
            int sn, mn; tile_of(it + 2, sn, mn);
            prefetch(sn, (it + 2) % 3);
            CP_COMMIT();
        }
    }

    // ---- epilogue: normalize by osum (== l), write hgemm<1> A-fragments ----
    const float inv0 = 1.f / osum[0], inv1 = 1.f / osum[2];
    const int b_ = bh >> 4, h_ = bh & 15;
    const size_t mb = ((size_t)b_ * 2048 + qt0 + wm) >> 4;   // global m16 block
#pragma unroll
    for (int c = 0; c < 4; c++) {
        uint4 w4;
        w4.x = pack_h2(o[2 * c][0] * inv0,     o[2 * c][1] * inv0);
        w4.y = pack_h2(o[2 * c][2] * inv1,     o[2 * c][3] * inv1);
        w4.z = pack_h2(o[2 * c + 1][0] * inv0, o[2 * c + 1][1] * inv0);
        w4.w = pack_h2(o[2 * c + 1][2] * inv1, o[2 * c + 1][3] * inv1);
        g_aF[(mb * 64 + (h_ * 4 + c)) * 32 + lane] = w4;
    }
}

// ---------------------------------------------------------------------------

extern "C" void kernel_launch(void* const* d_in, const int* in_sizes, int n_in,
                              void* d_out, int out_size)
{
    const float* x  = (const float*)d_in[0];
    const float* Wq = (const float*)d_in[1];
    const float* bq = (const float*)d_in[2];
    const float* Wk = (const float*)d_in[3];
    const float* bk = (const float*)d_in[4];
    const float* Wv = (const float*)d_in[5];
    const float* bv = (const float*)d_in[6];
    const float* Wo = (const float*)d_in[7];
    const float* bo = (const float*)d_in[8];

    cudaFuncSetAttribute(attn_mma, cudaFuncAttributeMaxDynamicSharedMemorySize, AT_SMEM);

    conv_aF<<<dim3(64, 16), 256>>>(x);                 // x -> A fragments
    conv_wF<<<dim3(8, 16, 4), 256>>>(Wq, Wk, Wv, Wo);

    hgemm<0><<<dim3(8, 64, 3), 256>>>(bq, bk, bv, nullptr);

    attn_mma<<<dim3(32, 64), 128, AT_SMEM>>>();        // overwrites g_aF with ctx frags

    hgemm<1><<<dim3(8, 64), 256>>>(bo, nullptr, nullptr, (float*)d_out);
}

// round 17
// speedup vs baseline: 1.0896x; 1.0234x over previous
#include <cuda_runtime.h>
#include <cuda_fp16.h>
#include <cstdint>

// Problem constants (fixed by setup_inputs)
#define TT    2048
#define DD    1024
#define HH    16
#define HDIM  64
#define BB    4
#define NBH   64        // B*H
#define MROWS 8192      // B*T

// ---------------- scratch (no cudaMalloc allowed) ----------------
__device__ uint4 g_aF[(size_t)512 * 64 * 32];      // A fragments [mb][ks][lane]; x-frags for hgemm<0>, ctx-frags for hgemm<1>
__device__ uint4 g_wF[(size_t)4 * 64 * 64 * 32];   // W fragments [z][nb][ks][lane]
__device__ uint4 g_qF[(size_t)NBH * 128 * 4 * 32]; // Q A-fragments [bh][t16][d16][lane]
__device__ __align__(16) __half g_kf[(size_t)NBH * TT * HDIM];   // [bh][t][d]
__device__ __align__(16) __half g_vTf[(size_t)NBH * HDIM * TT];  // [bh][d][t]

// ---------------- PTX helpers ----------------
__device__ __forceinline__ void mma_f16(float* c, const unsigned* a, const unsigned* b) {
    asm volatile(
        "mma.sync.aligned.m16n8k16.row.col.f32.f16.f16.f32 "
        "{%0,%1,%2,%3}, {%4,%5,%6,%7}, {%8,%9}, {%0,%1,%2,%3};\n"
        : "+f"(c[0]), "+f"(c[1]), "+f"(c[2]), "+f"(c[3])
        : "r"(a[0]), "r"(a[1]), "r"(a[2]), "r"(a[3]), "r"(b[0]), "r"(b[1]));
}

__device__ __forceinline__ void ldsm_x4(unsigned* r, unsigned addr) {
    asm volatile("ldmatrix.sync.aligned.m8n8.x4.shared.b16 {%0,%1,%2,%3}, [%4];\n"
                 : "=r"(r[0]), "=r"(r[1]), "=r"(r[2]), "=r"(r[3]) : "r"(addr));
}

__device__ __forceinline__ void cp16(unsigned smem, const void* g) {
    asm volatile("cp.async.ca.shared.global [%0], [%1], 16;\n" :: "r"(smem), "l"(g));
}
#define CP_COMMIT()  asm volatile("cp.async.commit_group;\n" ::: "memory")
#define CP_WAIT_1()  asm volatile("cp.async.wait_group 1;\n" ::: "memory")
#define CP_WAIT_0()  asm volatile("cp.async.wait_group 0;\n" ::: "memory")

__device__ __forceinline__ float ex2(float x) {
    float y; asm("ex2.approx.ftz.f32 %0, %1;\n" : "=f"(y) : "f"(x)); return y;
}

__device__ __forceinline__ unsigned h2ex2(unsigned x) {
    unsigned y; asm("ex2.approx.f16x2 %0, %1;\n" : "=r"(y) : "r"(x)); return y;
}

__device__ __forceinline__ unsigned pack_h2(float a, float b) {
    __half2 h = __floats2half2_rn(a, b);
    return *(unsigned*)&h;
}

#define QSCALE (0.125f * 1.4426950408889634f)   // hd^-0.5 * log2(e)

// ---------------- merged fragment-builder kernel ----------------
// blockIdx.x < 64 : x [m][k] fp32 -> A fragments g_aF[mb][ks][lane]
// blockIdx.x >= 64: W z=(x-64)>>3 -> B fragments g_wF[z][nb][ks][lane]
__global__ void __launch_bounds__(256) conv_frag(
    const float* __restrict__ xin,
    const float* __restrict__ Wq, const float* __restrict__ Wk,
    const float* __restrict__ Wv, const float* __restrict__ Wo)
{
    __shared__ __align__(16) char csm[4 * 6144];   // 4 k16 slabs, 128 rows x 48B
    const unsigned cb = (unsigned)__cvta_generic_to_shared(csm);
    const int tid = threadIdx.x;
    const int k0 = blockIdx.y * 64;

    if (blockIdx.x < 64) {
        const int m0 = blockIdx.x * 128;
        for (int i = 0; i < 32; i++) {
            int idx = tid + i * 256;              // 128m x 64k
            int m = idx >> 6, k = idx & 63;
            __half h = __float2half_rn(xin[(size_t)(m0 + m) * DD + k0 + k]);
            int slab = k >> 4, klo = k & 15;
            *(__half*)(csm + slab * 6144 + m * 48 + ((klo & 7) << 1) + ((klo >> 3) << 4)) = h;
        }
        __syncthreads();
        const int w = tid >> 5, lane = tid & 31;   // warp w -> m16 block w
#pragma unroll
        for (int s = 0; s < 4; s++) {
            unsigned afr[4];
            unsigned addr = cb + s * 6144 +
                (unsigned)((w * 16 + (lane & 15)) * 48 + ((lane >> 4) << 4));
            ldsm_x4(afr, addr);
            uint4 o4; o4.x = afr[0]; o4.y = afr[1]; o4.z = afr[2]; o4.w = afr[3];
            g_aF[(((size_t)(m0 >> 4) + w) * 64 + (k0 >> 4) + s) * 32 + lane] = o4;
        }
    } else {
        const int z = (blockIdx.x - 64) >> 3;
        const int n0 = ((blockIdx.x - 64) & 7) * 128;
        const float* W = (z == 0) ? Wq : (z == 1) ? Wk : (z == 2) ? Wv : Wo;
        for (int i = 0; i < 32; i++) {
            int idx = tid + i * 256;
            int k = idx >> 7, n = idx & 127;
            float w = W[(size_t)(k0 + k) * DD + n0 + n];
            int slab = k >> 4, klo = k & 15;
            *(__half*)(csm + slab * 6144 + n * 48 + ((klo & 7) << 1) + ((klo >> 3) << 4)) =
                __float2half_rn(w);
        }
        __syncthreads();
        const int w = tid >> 5, lane = tid & 31;   // warp w -> n16 block w
#pragma unroll
        for (int s = 0; s < 4; s++) {
            unsigned bfr[4];
            unsigned addr = cb + s * 6144 +
                (unsigned)((w * 16 + ((lane >> 4) << 3) + (lane & 7)) * 48 +
                           (((lane >> 3) & 1) << 4));
            ldsm_x4(bfr, addr);
            uint4 o4; o4.x = bfr[0]; o4.y = bfr[1]; o4.z = bfr[2]; o4.w = bfr[3];
            g_wF[(((size_t)z * 64 + (n0 >> 4) + w) * 64 + (k0 >> 4) + s) * 32 + lane] = o4;
        }
    }
}

// ---------------------------------------------------------------------------
// fp16 tensor-core GEMM, zero shared memory, k16-slab software pipeline
// (ping-pong register buffers, one slab of LDG lookahead; no register copies).
// C tile 128x128, 256 threads (8 warps of m64 x n32).
// MODE 0: QKV. z==0 epilogue writes Q ATTN FRAGMENTS (g_qF) directly;
//         z==1 -> g_kf rows; z==2 -> g_vTf transposed rows.
// MODE 1: out projection (fp32 out + bias), A read from g_aF (ctx frags).
// ---------------------------------------------------------------------------
template<int MODE>
__global__ void __launch_bounds__(256, 2) hgemm(
    const float* __restrict__ biasA, const float* __restrict__ biasB,
    const float* __restrict__ biasC, float* __restrict__ outp)
{
    const int z = (MODE == 0) ? blockIdx.z : 3;
    const float* bias = (MODE == 0) ? ((z == 0) ? biasA : (z == 1) ? biasB : biasC)
                                    : biasA;

    const int t = threadIdx.x;
    const int bm = blockIdx.y << 7;
    const int bn = blockIdx.x << 7;
    const int wid = t >> 5, lane = t & 31;
    const int wm = (wid & 1) << 6;
    const int wn = (wid >> 1) << 5;

    float acc[4][4][4];
#pragma unroll
    for (int i = 0; i < 4; i++)
#pragma unroll
        for (int j = 0; j < 4; j++)
#pragma unroll
            for (int r = 0; r < 4; r++) acc[i][j][r] = 0.f;

    const uint4* aP  = g_aF + ((size_t)((bm + wm) >> 4) * 64) * 32 + lane;
    const uint4* b0p = g_wF + (((size_t)z * 64 + (bn >> 4) + (wn >> 4)) * 64) * 32 + lane;
    const uint4* b1p = b0p + 64 * 32;

    // one k16 slab load (4 A m16-frags + 2 B n16-frags)
    auto lda = [&](uint4* ab, uint4* bb, int ks) {
        const int o = ks * 32;
#pragma unroll
        for (int i = 0; i < 4; i++) ab[i] = aP[i * 2048 + o];
        bb[0] = b0p[o];
        bb[1] = b1p[o];
    };
    auto domma = [&](const uint4* ab, const uint4* bb) {
        unsigned bfr[8];
        *(uint4*)(bfr)     = bb[0];
        *(uint4*)(bfr + 4) = bb[1];
#pragma unroll
        for (int i = 0; i < 4; i++) {
            const unsigned* afr = (const unsigned*)&ab[i];
#pragma unroll
            for (int j = 0; j < 4; j++)
                mma_f16(acc[i][j], afr, bfr + 2 * j);
        }
    };

    uint4 a0[4], b0[2], a1[4], b1[2];
    lda(a0, b0, 0);
    for (int it = 0; it < 32; ++it) {          // 64 k16 slabs, 2 per iter
        lda(a1, b1, 2 * it + 1);               // prefetch odd slab
        domma(a0, b0);                         // compute even slab
        if (it < 31) lda(a0, b0, 2 * it + 2);  // prefetch next even slab
        domma(a1, b1);                         // compute odd slab
    }

    const int gg = lane >> 2, tg = lane & 3;

    if (MODE == 0 && z == 0) {
        // Q: write attn-ready A fragments (C-layout == A-fragment identity)
#pragma unroll
        for (int i = 0; i < 4; i++) {
            const int rowb = bm + wm + 16 * i;       // m16 block base
            const int t16  = (rowb & 2047) >> 4;
            const int b0_  = rowb >> 11;
#pragma unroll
            for (int cp = 0; cp < 2; cp++) {
                const int j0 = 2 * cp, j1 = j0 + 1;
                const int col0 = bn + wn + 8 * j0 + 2 * tg;
                const int col1 = col0 + 8;
                float a00 = (acc[i][j0][0] + bias[col0])     * QSCALE;
                float a01 = (acc[i][j0][1] + bias[col0 + 1]) * QSCALE;
                float a10 = (acc[i][j0][2] + bias[col0])     * QSCALE;
                float a11 = (acc[i][j0][3] + bias[col0 + 1]) * QSCALE;
                float c00 = (acc[i][j1][0] + bias[col1])     * QSCALE;
                float c01 = (acc[i][j1][1] + bias[col1 + 1]) * QSCALE;
                float c10 = (acc[i][j1][2] + bias[col1])     * QSCALE;
                float c11 = (acc[i][j1][3] + bias[col1 + 1]) * QSCALE;
                const int head  = col0 >> 6;
                const int chunk = (col0 & 63) >> 4;
                const int bh_   = b0_ * 16 + head;
                uint4 o4;
                o4.x = pack_h2(a00, a01);   // (r, klow)
                o4.y = pack_h2(a10, a11);   // (r+8, klow)
                o4.z = pack_h2(c00, c01);   // (r, k+8)
                o4.w = pack_h2(c10, c11);   // (r+8, k+8)
                g_qF[(((size_t)bh_ * 128 + t16) * 4 + chunk) * 32 + lane] = o4;
            }
        }
        return;
    }

#pragma unroll
    for (int i = 0; i < 4; i++) {
#pragma unroll
        for (int j = 0; j < 4; j++) {
            const int row = bm + wm + 16 * i + gg;
            const int col = bn + wn + 8 * j + 2 * tg;
            float v00 = acc[i][j][0] + bias[col];
            float v01 = acc[i][j][1] + bias[col + 1];
            float v10 = acc[i][j][2] + bias[col];
            float v11 = acc[i][j][3] + bias[col + 1];
            if (MODE == 0) {
                const int head = col >> 6, d = col & 63;
                const int b0_ = row >> 11, t0_ = row & 2047;
                const int t1_ = (row + 8) & 2047;
                const int bh_ = b0_ * 16 + head;
                if (z == 2) {
                    size_t r0 = ((size_t)bh_ * 64 + d) * 2048;
                    size_t r1 = ((size_t)bh_ * 64 + d + 1) * 2048;
                    g_vTf[r0 + t0_] = __float2half_rn(v00);
                    g_vTf[r1 + t0_] = __float2half_rn(v01);
                    g_vTf[r0 + t1_] = __float2half_rn(v10);
                    g_vTf[r1 + t1_] = __float2half_rn(v11);
                } else {   // z == 1 : K rows
                    size_t o0 = ((size_t)bh_ * 2048 + t0_) * 64 + d;
                    size_t o1 = ((size_t)bh_ * 2048 + t1_) * 64 + d;
                    *(unsigned*)(g_kf + o0) = pack_h2(v00, v01);
                    *(unsigned*)(g_kf + o1) = pack_h2(v10, v11);
                }
            } else {
                outp[(size_t)row * DD + col]           = v00;
                outp[(size_t)row * DD + col + 1]       = v01;
                outp[(size_t)(row + 8) * DD + col]     = v10;
                outp[(size_t)(row + 8) * DD + col + 1] = v11;
            }
        }
    }
}

// ---------------------------------------------------------------------------
// fp16 tensor-core BD3LM attention (unchanged from R16 — 77.7us)
// ---------------------------------------------------------------------------
#define AT_PITCH  144
#define AT_ARR    (64 * AT_PITCH)     // 9216
#define AT_BUF    (2 * AT_ARR)        // 18432 (K, V)
#define AT_SMEM   (3 * AT_BUF)        // 55296

__global__ void __launch_bounds__(128, 4) attn_mma()
{
    extern __shared__ __align__(16) char dsm[];
    const unsigned sb = (unsigned)__cvta_generic_to_shared(dsm);

    const int bi = blockIdx.x;
    // heavy-first ordering: xt qt has qt+2 tiles, x0 qt has qt-15
    const int qt = (bi & 1) ? (31 - (bi >> 1)) : (15 - (bi >> 1));
    const int bh = blockIdx.y;
    const int qt0 = qt << 6;
    const int tid = threadIdx.x;
    const int lane = tid & 31, warp = tid >> 5;
    const int wm = warp << 4;
    const int g = lane >> 2, tq = lane & 3;

    // ---- Q fragments via LDG (prebuilt by hgemm<0> z==0) ----
    unsigned qf[4][4];
    {
        const size_t t16 = (size_t)bh * 128 + ((qt0 + wm) >> 4);
#pragma unroll
        for (int c = 0; c < 4; c++) {
            uint4 v = g_qF[(t16 * 4 + c) * 32 + lane];
            qf[c][0] = v.x; qf[c][1] = v.y; qf[c][2] = v.z; qf[c][3] = v.w;
        }
    }

    float o[8][4];
#pragma unroll
    for (int j = 0; j < 8; j++)
#pragma unroll
        for (int k = 0; k < 4; k++) o[j][k] = 0.f;
    float osum[4] = {0.f, 0.f, 0.f, 0.f};   // all-ones column: becomes l
    float m0 = -1e30f, m1 = -1e30f;

    const bool is_x0 = (qt >= 16);
    const int nfull  = is_x0 ? (qt - 16) : qt;
    const int ntiles = nfull + (is_x0 ? 1 : 2);

    auto tile_of = [&](int it, int& s, int& mode) {
        if (it < nfull)        { s = 1024 + (it << 6); mode = 0; }
        else if (is_x0)        { s = qt0;              mode = 1; }
        else if (it == nfull)  { s = 1024 + qt0;       mode = 2; }
        else                   { s = qt0;              mode = 3; }
    };

    auto prefetch = [&](int s, int buf) {
        unsigned dstb = sb + buf * AT_BUF;
#pragma unroll
        for (int i = 0; i < 8; i++) {
            int idx = tid + (i << 7);
            int arr = idx >> 9, rem = idx & 511;
            int r = rem >> 3, c = rem & 7;
            const __half* src = (arr == 0)
                ? g_kf  + ((size_t)bh * 2048 + s + r) * 64 + c * 8
                : g_vTf + ((size_t)bh * 64 + r) * 2048 + s + c * 8;
            cp16(dstb + arr * AT_ARR + r * AT_PITCH + c * 16, src);
        }
    };

    {
        int s0, md; tile_of(0, s0, md);
        prefetch(s0, 0);
        CP_COMMIT();
        if (ntiles > 1) { int s1; tile_of(1, s1, md); prefetch(s1, 1); }
        CP_COMMIT();    // commit even if empty: keeps group counting uniform
    }

    const unsigned b_off = (unsigned)((((lane >> 4) << 3) + (lane & 7)) * AT_PITCH +
                                      (((lane >> 3) & 1) << 4));
    const unsigned onesb[2] = {0x3C003C00u, 0x3C003C00u};   // fp16 1.0 x4

    for (int it = 0; it < ntiles; ++it) {
        int s_, mode; tile_of(it, s_, mode);
        if (it < ntiles - 1) { CP_WAIT_1(); } else { CP_WAIT_0(); }
        __syncthreads();   // tile 'it' ready; all warps done reading it-1

        const unsigned base = sb + (it % 3) * AT_BUF;

        // ---- S = Q K^T ----
        float sc[8][4];
#pragma unroll
        for (int j = 0; j < 8; j++)
#pragma unroll
            for (int k = 0; k < 4; k++) sc[j][k] = 0.f;

#pragma unroll
        for (int c = 0; c < 4; c++) {
#pragma unroll
            for (int p = 0; p < 4; p++) {
                unsigned kb[4];
                ldsm_x4(kb, base + (p << 4) * AT_PITCH + b_off + c * 32);
                mma_f16(sc[2 * p],     qf[c], kb);
                mma_f16(sc[2 * p + 1], qf[c], kb + 2);
            }
        }

        // ---- mask (boundary tiles only): block index = idx>>2 ----
        if (mode) {
#pragma unroll
            for (int j = 0; j < 8; j++)
#pragma unroll
                for (int k = 0; k < 4; k++) {
                    int r = wm + g + ((k >> 1) << 3);
                    int c = (j << 3) + (tq << 1) + (k & 1);
                    int r2 = r >> 2, c2 = c >> 2;
                    bool ok = (mode == 1) ? (c2 <= r2) :
                              (mode == 2) ? (c2 <  r2) : (c2 == r2);
                    if (!ok) sc[j][k] = -1e30f;
                }
        }

        // ---- online softmax: max (fp32) then fp16x2 exp -> P fragments ----
        float t0 = -1e30f, t1 = -1e30f;
#pragma unroll
        for (int j = 0; j < 8; j++) {
            t0 = fmaxf(t0, fmaxf(sc[j][0], sc[j][1]));
            t1 = fmaxf(t1, fmaxf(sc[j][2], sc[j][3]));
        }
        t0 = fmaxf(t0, __shfl_xor_sync(0xffffffffu, t0, 1));
        t0 = fmaxf(t0, __shfl_xor_sync(0xffffffffu, t0, 2));
        t1 = fmaxf(t1, __shfl_xor_sync(0xffffffffu, t1, 1));
        t1 = fmaxf(t1, __shfl_xor_sync(0xffffffffu, t1, 2));
        const float mn0 = fmaxf(m0, t0), mn1 = fmaxf(m1, t1);
        const float r0 = ex2(m0 - mn0), r1 = ex2(m1 - mn1);
        m0 = mn0; m1 = mn1;

        unsigned ph[8], pl[8];   // P fp16x2: rows g / g+8
#pragma unroll
        for (int j = 0; j < 8; j++) {
            ph[j] = h2ex2(pack_h2(sc[j][0] - mn0, sc[j][1] - mn0));
            pl[j] = h2ex2(pack_h2(sc[j][2] - mn1, sc[j][3] - mn1));
        }

        // rescale accumulators (osum follows the same recurrence -> final l)
#pragma unroll
        for (int j = 0; j < 8; j++) {
            o[j][0] *= r0; o[j][1] *= r0;
            o[j][2] *= r1; o[j][3] *= r1;
        }
        osum[0] *= r0; osum[1] *= r0;
        osum[2] *= r1; osum[3] *= r1;

        // ---- O += P V ; osum += P @ ones ----
#pragma unroll
        for (int c = 0; c < 4; c++) {
            unsigned pf[4];
            pf[0] = ph[2 * c];     pf[1] = pl[2 * c];
            pf[2] = ph[2 * c + 1]; pf[3] = pl[2 * c + 1];
            mma_f16(osum, pf, onesb);
#pragma unroll
            for (int p = 0; p < 4; p++) {
                unsigned vb[4];
                ldsm_x4(vb, base + AT_ARR + (p << 4) * AT_PITCH + b_off + c * 32);
                mma_f16(o[2 * p],     pf, vb);
                mma_f16(o[2 * p + 1], pf, vb + 2);
            }
        }

        if (it + 2 < ntiles) {   // refill buffer consumed at it-1
            int sn, mn; tile_of(it + 2, sn, mn);
            prefetch(sn, (it + 2) % 3);
            CP_COMMIT();
        }
    }

    // ---- epilogue: normalize by osum (== l), write hgemm<1> A-fragments ----
    const float inv0 = 1.f / osum[0], inv1 = 1.f / osum[2];
    const int b_ = bh >> 4, h_ = bh & 15;
    const size_t mb = ((size_t)b_ * 2048 + qt0 + wm) >> 4;   // global m16 block
#pragma unroll
    for (int c = 0; c < 4; c++) {
        uint4 w4;
        w4.x = pack_h2(o[2 * c][0] * inv0,     o[2 * c][1] * inv0);
        w4.y = pack_h2(o[2 * c][2] * inv1,     o[2 * c][3] * inv1);
        w4.z = pack_h2(o[2 * c + 1][0] * inv0, o[2 * c + 1][1] * inv0);
        w4.w = pack_h2(o[2 * c + 1][2] * inv1, o[2 * c + 1][3] * inv1);
        g_aF[(mb * 64 + (h_ * 4 + c)) * 32 + lane] = w4;
    }
}

// ---------------------------------------------------------------------------

extern "C" void kernel_launch(void* const* d_in, const int* in_sizes, int n_in,
                              void* d_out, int out_size)
{
    const float* x  = (const float*)d_in[0];
    const float* Wq = (const float*)d_in[1];
    const float* bq = (const float*)d_in[2];
    const float* Wk = (const float*)d_in[3];
    const float* bk = (const float*)d_in[4];
    const float* Wv = (const float*)d_in[5];
    const float* bv = (const float*)d_in[6];
    const float* Wo = (const float*)d_in[7];
    const float* bo = (const float*)d_in[8];

    cudaFuncSetAttribute(attn_mma, cudaFuncAttributeMaxDynamicSharedMemorySize, AT_SMEM);

    conv_frag<<<dim3(96, 16), 256>>>(x, Wq, Wk, Wv, Wo);   // x->aF (x<64), W->wF (x>=64)

    hgemm<0><<<dim3(8, 64, 3), 256>>>(bq, bk, bv, nullptr);

    attn_mma<<<dim3(32, 64), 128, AT_SMEM>>>();            // overwrites g_aF with ctx frags

    hgemm<1><<<dim3(8, 64), 256>>>(bo, nullptr, nullptr, (float*)d_out);
}